// round 3
// baseline (speedup 1.0000x reference)
#include <cuda_runtime.h>
#include <cuda_fp16.h>
#include <cstdint>

// ---------------- scratch (no allocs allowed) ----------------
// QKV fp32: 768 x 4096
__device__ __align__(16) float  g_qkv[768 * 4096];
// normalized q,k and v in fp16, layout [head][s][d] = [8][4096][32]
__device__ __align__(16) __half g_qn[8 * 4096 * 32];
__device__ __align__(16) __half g_kn[8 * 4096 * 32];
__device__ __align__(16) __half g_vh[8 * 4096 * 32];
// attention output, layout [s][head][d] flattened == (256 x 4096) row-major view
__device__ __align__(16) float  g_o2[4096 * 256];

// ---------------- generic fp32 GEMM: C[M][N] = A[M][K] * B[K][N] ----------------
// BM=BN=128, BK=16, 256 threads, 8x8 per-thread microtile. M,N % 128 == 0, K % 16 == 0.
__global__ __launch_bounds__(256) void gemm128(const float* __restrict__ A,
                                               const float* __restrict__ B,
                                               float* __restrict__ C,
                                               int M, int N, int K) {
    __shared__ float As[16][128];
    __shared__ float Bs[16][132];

    const int tid = threadIdx.x;
    const int bm = blockIdx.y * 128;
    const int bn = blockIdx.x * 128;
    const int tx = tid & 15;   // n
    const int ty = tid >> 4;   // m

    float acc[8][8];
#pragma unroll
    for (int i = 0; i < 8; i++)
#pragma unroll
        for (int j = 0; j < 8; j++) acc[i][j] = 0.0f;

    for (int k0 = 0; k0 < K; k0 += 16) {
        // load A tile 128x16, store transposed As[k][m]
        {
            int r = tid >> 1, c = (tid & 1) * 8;
            const float* src = A + (size_t)(bm + r) * K + k0 + c;
            float4 v0 = *(const float4*)src;
            float4 v1 = *(const float4*)(src + 4);
            As[c + 0][r] = v0.x; As[c + 1][r] = v0.y; As[c + 2][r] = v0.z; As[c + 3][r] = v0.w;
            As[c + 4][r] = v1.x; As[c + 5][r] = v1.y; As[c + 6][r] = v1.z; As[c + 7][r] = v1.w;
        }
        // load B tile 16x128
        {
            int r = tid >> 4, c = (tid & 15) * 8;
            const float* src = B + (size_t)(k0 + r) * N + bn + c;
            *(float4*)&Bs[r][c]     = *(const float4*)src;
            *(float4*)&Bs[r][c + 4] = *(const float4*)(src + 4);
        }
        __syncthreads();
#pragma unroll
        for (int kk = 0; kk < 16; kk++) {
            float a[8], b[8];
            *(float4*)(a)     = *(float4*)&As[kk][ty * 8];
            *(float4*)(a + 4) = *(float4*)&As[kk][ty * 8 + 4];
            *(float4*)(b)     = *(float4*)&Bs[kk][tx * 8];
            *(float4*)(b + 4) = *(float4*)&Bs[kk][tx * 8 + 4];
#pragma unroll
            for (int i = 0; i < 8; i++)
#pragma unroll
                for (int j = 0; j < 8; j++) acc[i][j] = fmaf(a[i], b[j], acc[i][j]);
        }
        __syncthreads();
    }
#pragma unroll
    for (int i = 0; i < 8; i++) {
        float* dst = C + (size_t)(bm + ty * 8 + i) * N + bn + tx * 8;
        *(float4*)dst       = *(float4*)&acc[i][0];
        *(float4*)(dst + 4) = *(float4*)&acc[i][4];
    }
}

// ---------------- normalize + transpose + fp16 pack ----------------
// grid (64 s-tiles, 8 heads, 3 parts). part 0=q (norm), 1=k (norm), 2=v.
// src g_qkv[o][s], o = part*256 + head*32 + d; dst [head][s][d] fp16.
__global__ __launch_bounds__(256) void norm_pack_kernel() {
    const int s0   = blockIdx.x * 64;
    const int head = blockIdx.y;
    const int part = blockIdx.z;

    __shared__ float sm[32][65];
    __shared__ float inv[64];

    const float* src = g_qkv + (size_t)(part * 256 + head * 32) * 4096 + s0;
    for (int i = threadIdx.x; i < 32 * 64; i += 256) {
        int d = i >> 6, s = i & 63;
        sm[d][s] = src[(size_t)d * 4096 + s];
    }
    __syncthreads();

    if (part < 2) {
        if (threadIdx.x < 64) {
            int s = threadIdx.x;
            float a = 0.0f;
#pragma unroll
            for (int d = 0; d < 32; d++) a = fmaf(sm[d][s], sm[d][s], a);
            float n = sqrtf(a);
            inv[s] = 1.0f / fmaxf(n, 1e-12f);
        }
        __syncthreads();
    }

    __half* dst = (part == 0 ? g_qn : (part == 1 ? g_kn : g_vh)) +
                  ((size_t)head * 4096 + s0) * 32;
    for (int i = threadIdx.x; i < 2048; i += 256) {
        int s = i >> 5, d = i & 31;
        float v = sm[d][s];
        if (part < 2) v *= inv[s];
        dst[i] = __float2half(v);
    }
}

// ---------------- flash attention (mma.sync f16, fp32 accum) ----------------
__device__ __forceinline__ void mma16816(float c[4], const uint32_t a[4],
                                         uint32_t b0, uint32_t b1) {
    asm volatile(
        "mma.sync.aligned.m16n8k16.row.col.f32.f16.f16.f32 "
        "{%0,%1,%2,%3}, {%4,%5,%6,%7}, {%8,%9}, {%0,%1,%2,%3};\n"
        : "+f"(c[0]), "+f"(c[1]), "+f"(c[2]), "+f"(c[3])
        : "r"(a[0]), "r"(a[1]), "r"(a[2]), "r"(a[3]), "r"(b0), "r"(b1));
}

__device__ __forceinline__ uint32_t packh2(float x, float y) {
    __half2 h = __floats2half2_rn(x, y);   // low = x, high = y
    return *(uint32_t*)&h;
}

// grid (32 q-blocks, 8 heads), 256 threads (8 warps). BLOCK_Q=128, BLOCK_T=64.
// logits bounded by |temperature| (q,k unit vectors) -> single pass, no running max.
__global__ __launch_bounds__(256, 2) void attn_kernel(const float* __restrict__ temp_arr) {
    const int head = blockIdx.y;
    const int q0   = blockIdx.x * 128;

    __shared__ __half Qs[128][40];  // q rows, padded K-stride (bank-safe, 16B-aligned)
    __shared__ __half Ks[64][40];   // k rows [t][d]
    __shared__ __half Vt[32][72];   // v transposed [d][t]

    const int tid  = threadIdx.x;
    const int lane = tid & 31;
    const int warp = tid >> 5;
    const int g    = lane >> 2;     // group id (row within fragment)
    const int tq   = lane & 3;      // quad id (col pair)
    const float tmp = temp_arr[head];

    const __half* Qg = g_qn + ((size_t)head * 4096 + q0) * 32;
    const __half* Kg = g_kn + (size_t)head * 4096 * 32;
    const __half* Vg = g_vh + (size_t)head * 4096 * 32;

    // load Q tile 128x32 (once)
    {
        int r = tid >> 1, c = (tid & 1) * 16;
        const uint4* s = (const uint4*)(Qg + (size_t)r * 32 + c);
        uint4 v0 = s[0], v1 = s[1];
        *(uint4*)&Qs[r][c]     = v0;
        *(uint4*)&Qs[r][c + 8] = v1;
    }

    // prefetch first K/V tile into registers
    const int kr = tid >> 2;          // t row 0..63
    const int kc = (tid & 3) * 8;     // d col {0,8,16,24}
    uint4 kreg = *(const uint4*)(Kg + (size_t)kr * 32 + kc);
    uint4 vreg = *(const uint4*)(Vg + (size_t)kr * 32 + kc);

    __syncthreads();

    // Q A-fragments (persist across whole t loop)
    const int qrow = warp * 16 + g;
    uint32_t qa[2][4];
#pragma unroll
    for (int ks = 0; ks < 2; ks++) {
        int cb = ks * 16 + tq * 2;
        qa[ks][0] = *(const uint32_t*)&Qs[qrow][cb];
        qa[ks][1] = *(const uint32_t*)&Qs[qrow + 8][cb];
        qa[ks][2] = *(const uint32_t*)&Qs[qrow][cb + 8];
        qa[ks][3] = *(const uint32_t*)&Qs[qrow + 8][cb + 8];
    }

    float o[4][4];
#pragma unroll
    for (int i = 0; i < 4; i++)
#pragma unroll
        for (int j = 0; j < 4; j++) o[i][j] = 0.0f;
    float den0 = 0.0f, den1 = 0.0f;

    for (int it = 0; it < 64; it++) {
        // commit prefetched tile to smem
        *(uint4*)&Ks[kr][kc] = kreg;
        {
            const __half* vh = (const __half*)&vreg;
#pragma unroll
            for (int j = 0; j < 8; j++) Vt[kc + j][kr] = vh[j];
        }
        __syncthreads();
        if (it < 63) {  // prefetch next tile (overlaps with compute below)
            const size_t off = (size_t)((it + 1) * 64 + kr) * 32 + kc;
            kreg = *(const uint4*)(Kg + off);
            vreg = *(const uint4*)(Vg + off);
        }

        // S = Q @ K^T  (16 x 64 per warp)
        float s[8][4];
#pragma unroll
        for (int nt = 0; nt < 8; nt++) {
            s[nt][0] = s[nt][1] = s[nt][2] = s[nt][3] = 0.0f;
#pragma unroll
            for (int ks = 0; ks < 2; ks++) {
                uint32_t b0 = *(const uint32_t*)&Ks[nt * 8 + g][ks * 16 + tq * 2];
                uint32_t b1 = *(const uint32_t*)&Ks[nt * 8 + g][ks * 16 + tq * 2 + 8];
                mma16816(s[nt], qa[ks], b0, b1);
            }
        }

        // p = exp(t*(s-1)); accumulate row sums
        float l0 = 0.0f, l1 = 0.0f;
#pragma unroll
        for (int nt = 0; nt < 8; nt++) {
            float p0 = __expf(fmaf(tmp, s[nt][0], -tmp));
            float p1 = __expf(fmaf(tmp, s[nt][1], -tmp));
            float p2 = __expf(fmaf(tmp, s[nt][2], -tmp));
            float p3 = __expf(fmaf(tmp, s[nt][3], -tmp));
            s[nt][0] = p0; s[nt][1] = p1; s[nt][2] = p2; s[nt][3] = p3;
            l0 += p0 + p1;
            l1 += p2 + p3;
        }
        den0 += l0; den1 += l1;

        // O += P @ V   (A = P from registers, B = Vt)
#pragma unroll
        for (int ks = 0; ks < 4; ks++) {
            uint32_t pa[4];
            pa[0] = packh2(s[2 * ks][0],     s[2 * ks][1]);
            pa[1] = packh2(s[2 * ks][2],     s[2 * ks][3]);
            pa[2] = packh2(s[2 * ks + 1][0], s[2 * ks + 1][1]);
            pa[3] = packh2(s[2 * ks + 1][2], s[2 * ks + 1][3]);
#pragma unroll
            for (int nt = 0; nt < 4; nt++) {
                uint32_t b0 = *(const uint32_t*)&Vt[nt * 8 + g][ks * 16 + tq * 2];
                uint32_t b1 = *(const uint32_t*)&Vt[nt * 8 + g][ks * 16 + tq * 2 + 8];
                mma16816(o[nt], pa, b0, b1);
            }
        }
        __syncthreads();
    }

    // finalize: reduce denominators across the quad, scale, store
    den0 += __shfl_xor_sync(0xffffffffu, den0, 1);
    den0 += __shfl_xor_sync(0xffffffffu, den0, 2);
    den1 += __shfl_xor_sync(0xffffffffu, den1, 1);
    den1 += __shfl_xor_sync(0xffffffffu, den1, 2);
    const float i0 = 1.0f / den0;
    const float i1 = 1.0f / den1;

    const int sg0 = q0 + warp * 16 + g;
    const int sg1 = sg0 + 8;
#pragma unroll
    for (int nt = 0; nt < 4; nt++) {
        int d = nt * 8 + tq * 2;
        float2 r0 = make_float2(o[nt][0] * i0, o[nt][1] * i0);
        float2 r1 = make_float2(o[nt][2] * i1, o[nt][3] * i1);
        *(float2*)(g_o2 + (size_t)sg0 * 256 + head * 32 + d) = r0;
        *(float2*)(g_o2 + (size_t)sg1 * 256 + head * 32 + d) = r1;
    }
}

// ---------------- launch ----------------
extern "C" void kernel_launch(void* const* d_in, const int* in_sizes, int n_in,
                              void* d_out, int out_size) {
    const float* x      = (const float*)d_in[0];  // (1,256,64,64) = [256][4096]
    const float* w_qkv  = (const float*)d_in[1];  // (768,256)
    const float* w_proj = (const float*)d_in[2];  // (256,256)
    const float* temp   = (const float*)d_in[3];  // (8)
    float* out = (float*)d_out;                   // [256][4096]

    float* qkv_p = nullptr;
    float* o2_p  = nullptr;
    cudaGetSymbolAddress((void**)&qkv_p, g_qkv);
    cudaGetSymbolAddress((void**)&o2_p,  g_o2);

    // K1: QKV = Wqkv(768x256) @ X(256x4096)
    gemm128<<<dim3(4096 / 128, 768 / 128), 256>>>(w_qkv, x, qkv_p, 768, 4096, 256);
    // K2: normalize q,k; pack q,k,v fp16 [head][s][d]
    norm_pack_kernel<<<dim3(64, 8, 3), 256>>>();
    // K3: flash attention -> g_o2 ([s][head][d] == (256x4096) for the projection)
    attn_kernel<<<dim3(32, 8), 256>>>(temp);
    // K4: Y = Wproj(256x256) @ O2(256x4096)
    gemm128<<<dim3(4096 / 128, 256 / 128), 256>>>(w_proj, o2_p, out, 256, 4096, 256);
}

// round 6
// speedup vs baseline: 1.5590x; 1.5590x over previous
#include <cuda_runtime.h>
#include <cuda_fp16.h>
#include <cstdint>

// ---------------- scratch (no allocs allowed) ----------------
__device__ __align__(16) float  g_qkv[768 * 4096];
__device__ __align__(16) __half g_qn[8 * 4096 * 32];
__device__ __align__(16) __half g_kn[8 * 4096 * 32];
__device__ __align__(16) __half g_vh[8 * 4096 * 32];
__device__ __align__(16) float  g_o2[4096 * 256];

// ---------------- tf32 mma helpers ----------------
__device__ __forceinline__ uint32_t f2tf32(float f) {
    uint32_t r;
    asm("cvt.rna.tf32.f32 %0, %1;" : "=r"(r) : "f"(f));
    return r;
}
__device__ __forceinline__ void mma1688(float c[4], const uint32_t a[4],
                                        uint32_t b0, uint32_t b1) {
    asm volatile(
        "mma.sync.aligned.m16n8k8.row.col.f32.tf32.tf32.f32 "
        "{%0,%1,%2,%3}, {%4,%5,%6,%7}, {%8,%9}, {%0,%1,%2,%3};\n"
        : "+f"(c[0]), "+f"(c[1]), "+f"(c[2]), "+f"(c[3])
        : "r"(a[0]), "r"(a[1]), "r"(a[2]), "r"(a[3]), "r"(b0), "r"(b1));
}

// ---------------- tf32 tensor-core GEMM: C[M][N] = A[M][K] * B[K][N] ----------------
// BM=BN=128, BK=16, 256 threads (8 warps, 2m x 4n, each 64m x 32n). fp32 I/O.
__global__ __launch_bounds__(256) void gemm_tf32(const float* __restrict__ A,
                                                 const float* __restrict__ B,
                                                 float* __restrict__ C,
                                                 int M, int N, int K) {
    __shared__ float As[128][20];   // [m][k], pad 20 -> conflict-free frag loads
    __shared__ float Bs[16][136];   // [k][n], pad 136 -> conflict-free

    const int tid = threadIdx.x, lane = tid & 31, warp = tid >> 5;
    const int bm = blockIdx.y * 128, bn = blockIdx.x * 128;
    const int m_base = (warp & 1) * 64, n_base = (warp >> 1) * 32;
    const int g = lane >> 2, tq = lane & 3;

    float acc[4][4][4] = {};

    const int ar = tid >> 1, ac = (tid & 1) * 8;
    const int br = tid >> 4, bc = (tid & 15) * 8;
    const float* Ap = A + (size_t)(bm + ar) * K + ac;
    const float* Bp = B + (size_t)br * N + bn + bc;

    float4 a0v = *(const float4*)Ap, a1v = *(const float4*)(Ap + 4);
    float4 b0v = *(const float4*)Bp, b1v = *(const float4*)(Bp + 4);

    for (int k0 = 0; k0 < K; k0 += 16) {
        *(float4*)&As[ar][ac]     = a0v;
        *(float4*)&As[ar][ac + 4] = a1v;
        *(float4*)&Bs[br][bc]     = b0v;
        *(float4*)&Bs[br][bc + 4] = b1v;
        __syncthreads();
        if (k0 + 16 < K) {
            a0v = *(const float4*)(Ap + k0 + 16);
            a1v = *(const float4*)(Ap + k0 + 20);
            b0v = *(const float4*)(Bp + (size_t)(k0 + 16) * N);
            b1v = *(const float4*)(Bp + (size_t)(k0 + 16) * N + 4);
        }
#pragma unroll
        for (int ks = 0; ks < 2; ks++) {
            const int kk = ks * 8;
            uint32_t af[4][4];
#pragma unroll
            for (int mt = 0; mt < 4; mt++) {
                int r0 = m_base + mt * 16;
                af[mt][0] = f2tf32(As[r0 + g][kk + tq]);
                af[mt][1] = f2tf32(As[r0 + 8 + g][kk + tq]);
                af[mt][2] = f2tf32(As[r0 + g][kk + tq + 4]);
                af[mt][3] = f2tf32(As[r0 + 8 + g][kk + tq + 4]);
            }
            uint32_t bf[4][2];
#pragma unroll
            for (int nt = 0; nt < 4; nt++) {
                bf[nt][0] = f2tf32(Bs[kk + tq][n_base + nt * 8 + g]);
                bf[nt][1] = f2tf32(Bs[kk + tq + 4][n_base + nt * 8 + g]);
            }
#pragma unroll
            for (int mt = 0; mt < 4; mt++)
#pragma unroll
                for (int nt = 0; nt < 4; nt++)
                    mma1688(acc[mt][nt], af[mt], bf[nt][0], bf[nt][1]);
        }
        __syncthreads();
    }
#pragma unroll
    for (int mt = 0; mt < 4; mt++) {
        const int r0 = bm + m_base + mt * 16 + g;
#pragma unroll
        for (int nt = 0; nt < 4; nt++) {
            const int c0 = bn + n_base + nt * 8 + tq * 2;
            *(float2*)(C + (size_t)r0 * N + c0)       = make_float2(acc[mt][nt][0], acc[mt][nt][1]);
            *(float2*)(C + (size_t)(r0 + 8) * N + c0) = make_float2(acc[mt][nt][2], acc[mt][nt][3]);
        }
    }
}

// ---------------- normalize + transpose + fp16 pack ----------------
__global__ __launch_bounds__(256) void norm_pack_kernel() {
    const int s0 = blockIdx.x * 64;
    const int head = blockIdx.y;
    const int part = blockIdx.z;

    __shared__ float sm[32][65];
    __shared__ float inv[64];

    const float* src = g_qkv + (size_t)(part * 256 + head * 32) * 4096 + s0;
    for (int i = threadIdx.x; i < 32 * 64; i += 256) {
        int d = i >> 6, s = i & 63;
        sm[d][s] = src[(size_t)d * 4096 + s];
    }
    __syncthreads();

    if (part < 2) {
        if (threadIdx.x < 64) {
            int s = threadIdx.x;
            float a = 0.0f;
#pragma unroll
            for (int d = 0; d < 32; d++) a = fmaf(sm[d][s], sm[d][s], a);
            float n = sqrtf(a);
            inv[s] = 1.0f / fmaxf(n, 1e-12f);
        }
        __syncthreads();
    }

    __half* dst = (part == 0 ? g_qn : (part == 1 ? g_kn : g_vh)) +
                  ((size_t)head * 4096 + s0) * 32;
    for (int i = threadIdx.x; i < 2048; i += 256) {
        int s = i >> 5, d = i & 31;
        float v = sm[d][s];
        if (part < 2) v *= inv[s];
        dst[i] = __float2half(v);
    }
}

// ---------------- flash attention (mma.sync f16, fp32 accum, ldmatrix) ----------------
__device__ __forceinline__ void mma16816(float c[4], const uint32_t a[4],
                                         uint32_t b0, uint32_t b1) {
    asm volatile(
        "mma.sync.aligned.m16n8k16.row.col.f32.f16.f16.f32 "
        "{%0,%1,%2,%3}, {%4,%5,%6,%7}, {%8,%9}, {%0,%1,%2,%3};\n"
        : "+f"(c[0]), "+f"(c[1]), "+f"(c[2]), "+f"(c[3])
        : "r"(a[0]), "r"(a[1]), "r"(a[2]), "r"(a[3]), "r"(b0), "r"(b1));
}
__device__ __forceinline__ uint32_t packh2(float x, float y) {
    __half2 h = __floats2half2_rn(x, y);
    return *(uint32_t*)&h;
}
__device__ __forceinline__ void ldsm4(uint32_t& r0, uint32_t& r1, uint32_t& r2,
                                      uint32_t& r3, uint32_t addr) {
    asm volatile("ldmatrix.sync.aligned.m8n8.x4.shared.b16 {%0,%1,%2,%3}, [%4];"
                 : "=r"(r0), "=r"(r1), "=r"(r2), "=r"(r3) : "r"(addr));
}
__device__ __forceinline__ void ldsm4t(uint32_t& r0, uint32_t& r1, uint32_t& r2,
                                       uint32_t& r3, uint32_t addr) {
    asm volatile("ldmatrix.sync.aligned.m8n8.x4.trans.shared.b16 {%0,%1,%2,%3}, [%4];"
                 : "=r"(r0), "=r"(r1), "=r"(r2), "=r"(r3) : "r"(addr));
}

// grid (32 q-blocks, 8 heads), 256 threads. BLOCK_Q=128, BLOCK_T=64, double-buffered.
__global__ __launch_bounds__(256, 2) void attn_kernel(const float* __restrict__ temp_arr) {
    const int head = blockIdx.y;
    const int q0   = blockIdx.x * 128;

    __shared__ alignas(16) __half Qs[128][40];
    __shared__ alignas(16) __half Ks[2][64][40];   // [t][d]
    __shared__ alignas(16) __half Vs[2][64][40];   // [t][d]

    const int tid  = threadIdx.x;
    const int lane = tid & 31;
    const int warp = tid >> 5;
    const int g    = lane >> 2;
    const int tq   = lane & 3;
    const float tmp = temp_arr[head];

    const __half* Qg = g_qn + ((size_t)head * 4096 + q0) * 32;
    const __half* Kg = g_kn + (size_t)head * 4096 * 32;
    const __half* Vg = g_vh + (size_t)head * 4096 * 32;

    // Q tile 128x32
    {
        int r = tid >> 1, c = (tid & 1) * 16;
        const uint4* s = (const uint4*)(Qg + (size_t)r * 32 + c);
        uint4 v0 = s[0], v1 = s[1];
        *(uint4*)&Qs[r][c]     = v0;
        *(uint4*)&Qs[r][c + 8] = v1;
    }

    // tile 0 -> buf0, prefetch tile 1 into regs
    const int kr = tid >> 2, kc = (tid & 3) * 8;
    {
        uint4 k0v = *(const uint4*)(Kg + (size_t)kr * 32 + kc);
        uint4 v0v = *(const uint4*)(Vg + (size_t)kr * 32 + kc);
        *(uint4*)&Ks[0][kr][kc] = k0v;
        *(uint4*)&Vs[0][kr][kc] = v0v;
    }
    uint4 kreg = *(const uint4*)(Kg + (size_t)(64 + kr) * 32 + kc);
    uint4 vreg = *(const uint4*)(Vg + (size_t)(64 + kr) * 32 + kc);
    __syncthreads();

    // Q A-fragments (persist)
    const int qrow = warp * 16 + g;
    uint32_t qa[2][4];
#pragma unroll
    for (int ks = 0; ks < 2; ks++) {
        int cb = ks * 16 + tq * 2;
        qa[ks][0] = *(const uint32_t*)&Qs[qrow][cb];
        qa[ks][1] = *(const uint32_t*)&Qs[qrow + 8][cb];
        qa[ks][2] = *(const uint32_t*)&Qs[qrow][cb + 8];
        qa[ks][3] = *(const uint32_t*)&Qs[qrow + 8][cb + 8];
    }

    // ldmatrix per-lane address components (in halves)
    const uint32_t ksm = (uint32_t)__cvta_generic_to_shared(&Ks[0][0][0]);
    const uint32_t vsm = (uint32_t)__cvta_generic_to_shared(&Vs[0][0][0]);
    const int srow = (lane & 7) + ((lane >> 4) & 1) * 8;  // non-trans (K)
    const int scol = ((lane >> 3) & 1) * 8;
    const int trow = (lane & 7) + ((lane >> 3) & 1) * 8;  // trans (V)
    const int tcol = ((lane >> 4) & 1) * 8;

    float o[4][4] = {};
    float den0 = 0.0f, den1 = 0.0f;

    for (int it = 0; it < 64; it++) {
        const int buf = it & 1;
        if (it < 63) {
            *(uint4*)&Ks[buf ^ 1][kr][kc] = kreg;
            *(uint4*)&Vs[buf ^ 1][kr][kc] = vreg;
            if (it < 62) {
                const size_t off = (size_t)((it + 2) * 64 + kr) * 32 + kc;
                kreg = *(const uint4*)(Kg + off);
                vreg = *(const uint4*)(Vg + off);
            }
        }

        const uint32_t kbase = ksm + (uint32_t)(buf * 64 * 40) * 2;
        const uint32_t vbase = vsm + (uint32_t)(buf * 64 * 40) * 2;

        // S = Q @ K^T (16 x 64 per warp)
        float s[8][4] = {};
#pragma unroll
        for (int ks = 0; ks < 2; ks++) {
#pragma unroll
            for (int np = 0; np < 4; np++) {
                uint32_t r0, r1, r2, r3;
                uint32_t addr = kbase + (uint32_t)((np * 16 + srow) * 40 + ks * 16 + scol) * 2;
                ldsm4(r0, r1, r2, r3, addr);
                mma16816(s[2 * np],     qa[ks], r0, r1);
                mma16816(s[2 * np + 1], qa[ks], r2, r3);
            }
        }

        // p = exp(t*(s-1)); row sums
        float l0 = 0.0f, l1 = 0.0f;
#pragma unroll
        for (int nt = 0; nt < 8; nt++) {
            float p0 = __expf(fmaf(tmp, s[nt][0], -tmp));
            float p1 = __expf(fmaf(tmp, s[nt][1], -tmp));
            float p2 = __expf(fmaf(tmp, s[nt][2], -tmp));
            float p3 = __expf(fmaf(tmp, s[nt][3], -tmp));
            s[nt][0] = p0; s[nt][1] = p1; s[nt][2] = p2; s[nt][3] = p3;
            l0 += p0 + p1;
            l1 += p2 + p3;
        }
        den0 += l0; den1 += l1;

        // O += P @ V (B frags via ldmatrix.trans on row-major V)
#pragma unroll
        for (int ks = 0; ks < 4; ks++) {
            uint32_t pa[4];
            pa[0] = packh2(s[2 * ks][0],     s[2 * ks][1]);
            pa[1] = packh2(s[2 * ks][2],     s[2 * ks][3]);
            pa[2] = packh2(s[2 * ks + 1][0], s[2 * ks + 1][1]);
            pa[3] = packh2(s[2 * ks + 1][2], s[2 * ks + 1][3]);
#pragma unroll
            for (int np = 0; np < 2; np++) {
                uint32_t r0, r1, r2, r3;
                uint32_t addr = vbase + (uint32_t)((ks * 16 + trow) * 40 + np * 16 + tcol) * 2;
                ldsm4t(r0, r1, r2, r3, addr);
                mma16816(o[2 * np],     pa, r0, r1);
                mma16816(o[2 * np + 1], pa, r2, r3);
            }
        }
        __syncthreads();
    }

    // finalize
    den0 += __shfl_xor_sync(0xffffffffu, den0, 1);
    den0 += __shfl_xor_sync(0xffffffffu, den0, 2);
    den1 += __shfl_xor_sync(0xffffffffu, den1, 1);
    den1 += __shfl_xor_sync(0xffffffffu, den1, 2);
    const float i0 = 1.0f / den0;
    const float i1 = 1.0f / den1;

    const int sg0 = q0 + warp * 16 + g;
    const int sg1 = sg0 + 8;
#pragma unroll
    for (int nt = 0; nt < 4; nt++) {
        int d = nt * 8 + tq * 2;
        *(float2*)(g_o2 + (size_t)sg0 * 256 + head * 32 + d) =
            make_float2(o[nt][0] * i0, o[nt][1] * i0);
        *(float2*)(g_o2 + (size_t)sg1 * 256 + head * 32 + d) =
            make_float2(o[nt][2] * i1, o[nt][3] * i1);
    }
}

// ---------------- launch ----------------
extern "C" void kernel_launch(void* const* d_in, const int* in_sizes, int n_in,
                              void* d_out, int out_size) {
    const float* x      = (const float*)d_in[0];
    const float* w_qkv  = (const float*)d_in[1];
    const float* w_proj = (const float*)d_in[2];
    const float* temp   = (const float*)d_in[3];
    float* out = (float*)d_out;

    float* qkv_p = nullptr;
    float* o2_p  = nullptr;
    cudaGetSymbolAddress((void**)&qkv_p, g_qkv);
    cudaGetSymbolAddress((void**)&o2_p,  g_o2);

    // K1: QKV = Wqkv(768x256) @ X(256x4096)  [tf32 tensor cores]
    gemm_tf32<<<dim3(4096 / 128, 768 / 128), 256>>>(w_qkv, x, qkv_p, 768, 4096, 256);
    // K2: normalize q,k; pack q,k,v fp16 [head][s][d]
    norm_pack_kernel<<<dim3(64, 8, 3), 256>>>();
    // K3: flash attention -> g_o2
    attn_kernel<<<dim3(32, 8), 256>>>(temp);
    // K4: Y = Wproj(256x256) @ O2(256x4096)  [tf32 tensor cores]
    gemm_tf32<<<dim3(4096 / 128, 256 / 128), 256>>>(w_proj, o2_p, out, 256, 4096, 256);
}